// round 16
// baseline (speedup 1.0000x reference)
#include <cuda_runtime.h>
#include <cstdint>

// ---------------------------------------------------------------------------
// Fused 2-layer LSTM, S=4096, B=64, I=14, H=256, O=1 (gate order i,f,g,o)
// 8 clusters x 16 CTAs (one batch group per cluster). h exchange: st.async
// into all 16 peers' smem + byte-counting mbarriers (8192B/phase). One
// barrier.cluster per step orders reads-before-overwrite and arm-before-bytes.
// Compute: thread=(kq,jl,b); all kq do a layer0 k-quarter; kq0/kq1 the Wih1
// halves; kq2/kq3 the Whh1 halves; kq3 folds x[t]; kq0 finalizes L0; kq1
// finalizes L1 + FC. Partials combined via smem + one __syncthreads.
// ---------------------------------------------------------------------------

#define S_LEN  4096
#define BATCH  64
#define IN0    14
#define HID    256
#define NB     128
#define NT     512
#define GCTAS  16
#define JL     16
#define BG     8
#define TXB    8192u      // 16 CTAs x 512B per buffer per phase

// ---- helpers ---------------------------------------------------------------
static __device__ __forceinline__ unsigned long long pack2(float x, float y) {
    unsigned long long r;
    asm("mov.b64 %0, {%1,%2};" : "=l"(r) : "f"(x), "f"(y));
    return r;
}
static __device__ __forceinline__ void unpack2(unsigned long long v, float& x, float& y) {
    asm("mov.b64 {%0,%1}, %2;" : "=f"(x), "=f"(y) : "l"(v));
}
static __device__ __forceinline__ unsigned long long ffma2(unsigned long long a,
                                                           unsigned long long b,
                                                           unsigned long long c) {
    unsigned long long d;
    asm("fma.rn.f32x2 %0, %1, %2, %3;" : "=l"(d) : "l"(a), "l"(b), "l"(c));
    return d;
}
static __device__ __forceinline__ float sum2(unsigned long long v) {
    float lo, hi; unpack2(v, lo, hi); return lo + hi;
}
static __device__ __forceinline__ float sigmoidf_(float v) {
    return 1.0f / (1.0f + __expf(-v));
}
static __device__ __forceinline__ float tanh_acc(float v) {
    float a = fabsf(v);
    float e = __expf(-2.0f * a);
    float r = __fdividef(1.0f - e, 1.0f + e);
    return v < 0.0f ? -r : r;
}
static __device__ __forceinline__ float warp_reduce(float p) {
    #pragma unroll
    for (int o = 16; o > 0; o >>= 1) p += __shfl_xor_sync(0xffffffffu, p, o);
    return p;
}
static __device__ __forceinline__ void mbar_init(uint32_t a, uint32_t cnt) {
    asm volatile("mbarrier.init.shared.b64 [%0], %1;" :: "r"(a), "r"(cnt) : "memory");
}
static __device__ __forceinline__ void mbar_arrive_tx(uint32_t a, uint32_t bytes) {
    asm volatile("mbarrier.arrive.expect_tx.shared.b64 _, [%0], %1;"
                 :: "r"(a), "r"(bytes) : "memory");
}
static __device__ __forceinline__ void mbar_wait_parity(uint32_t addr, uint32_t parity) {
    asm volatile(
        "{\n\t.reg .pred P;\n"
        "MW_%=:\n\t"
        "mbarrier.try_wait.parity.acquire.cluster.shared::cta.b64 P, [%0], %1;\n\t"
        "@!P bra MW_%=;\n\t}"
        :: "r"(addr), "r"(parity) : "memory");
}
static __device__ __forceinline__ uint32_t ctarank_() {
    uint32_t r; asm("mov.u32 %0, %%cluster_ctarank;" : "=r"(r)); return r;
}
static __device__ __forceinline__ uint32_t mapa_(uint32_t a, uint32_t rank) {
    uint32_t d;
    asm("mapa.shared::cluster.u32 %0, %1, %2;" : "=r"(d) : "r"(a), "r"(rank));
    return d;
}
static __device__ __forceinline__ void st_async16(uint32_t dst, float4 v, uint32_t mbar) {
    asm volatile(
        "st.async.shared::cluster.mbarrier::complete_tx::bytes.v4.b32 "
        "[%0], {%1,%2,%3,%4}, [%5];"
        :: "r"(dst), "r"(__float_as_uint(v.x)), "r"(__float_as_uint(v.y)),
           "r"(__float_as_uint(v.z)), "r"(__float_as_uint(v.w)), "r"(mbar)
        : "memory");
}
#define CLUSTER_ARRIVE() asm volatile("barrier.cluster.arrive.aligned;" ::: "memory")
#define CLUSTER_WAIT()   asm volatile("barrier.cluster.wait.aligned;"   ::: "memory")

template<int N>
static __device__ __forceinline__ void gemmN(const unsigned long long* hp,
                                             const unsigned long long* wq,
                                             unsigned long long& a0, unsigned long long& a1,
                                             unsigned long long& a2, unsigned long long& a3) {
    #pragma unroll 8
    for (int kp = 0; kp < N; ++kp) {
        unsigned long long hv = hp[kp*8];
        const unsigned long long* w = wq + kp*64;
        ulonglong2 wA = *(const ulonglong2*)(w);
        ulonglong2 wB = *(const ulonglong2*)(w + 2);
        a0 = ffma2(hv, wA.x, a0); a1 = ffma2(hv, wA.y, a1);
        a2 = ffma2(hv, wB.x, a2); a3 = ffma2(hv, wB.y, a3);
    }
}

// ---- smem layout (bytes) ---------------------------------------------------
#define SH_W0    0          // 65536  Whh0  ull slot (kp*16+jl)*4+gate
#define SH_WI1   65536      // 65536  Wih1
#define SH_WH1   131072     // 65536  Whh1
#define SH_WI0   196608     // 3584   float4 wi0[16][14]
#define SH_H0    200192     // 8192   h0 group buffer, ull[kp128][b8]
#define SH_H1    208384     // 8192   h1 group buffer
#define SH_PL0   216576     // 6144   float4[3][128]
#define SH_PL1   222720     // 6144   float4[3][128]
#define SH_STG0  228864     // 512    this CTA's h0 slice (send staging)
#define SH_STG1  229376     // 512    this CTA's h1 slice
#define SH_X     229888     // 896    float[2][112]
#define SH_RED   230784     // 32
#define SH_MBAR  230816     // 16     mb0, mb1
#define SMEM_TOTAL 230832

extern "C" __global__ void __launch_bounds__(NT, 1)
lstm_cluster(const float* __restrict__ x,    const float* __restrict__ h0in,
             const float* __restrict__ c0,
             const float* __restrict__ Wih0, const float* __restrict__ Whh0,
             const float* __restrict__ bih0, const float* __restrict__ bhh0,
             const float* __restrict__ Wih1, const float* __restrict__ Whh1,
             const float* __restrict__ bih1, const float* __restrict__ bhh1,
             const float* __restrict__ Wfc,  const float* __restrict__ bfc,
             float* __restrict__ out)
{
    extern __shared__ char smem[];
    unsigned long long* w0u    = (unsigned long long*)(smem + SH_W0);
    unsigned long long* wi1u   = (unsigned long long*)(smem + SH_WI1);
    unsigned long long* wh1u   = (unsigned long long*)(smem + SH_WH1);
    float4*             wi0    = (float4*)(smem + SH_WI0);
    unsigned long long* sh_h0u = (unsigned long long*)(smem + SH_H0);
    unsigned long long* sh_h1u = (unsigned long long*)(smem + SH_H1);
    float*              sh_h0f = (float*)(smem + SH_H0);
    float*              sh_h1f = (float*)(smem + SH_H1);
    float4*             pl0    = (float4*)(smem + SH_PL0);
    float4*             pl1    = (float4*)(smem + SH_PL1);
    float*              stg0   = (float*)(smem + SH_STG0);
    float*              stg1   = (float*)(smem + SH_STG1);
    float*              shx    = (float*)(smem + SH_X);
    float*              red4   = (float*)(smem + SH_RED);

    const uint32_t sb  = (uint32_t)__cvta_generic_to_shared(smem);
    const uint32_t mb0 = sb + SH_MBAR;
    const uint32_t mb1 = sb + SH_MBAR + 8;

    const int tid  = threadIdx.x;
    const int gid  = blockIdx.x >> 4;
    const int rank = (int)ctarank_();
    const int kq = tid >> 7, f = tid & 127, jl = f >> 3, b = f & 7;
    const int jglob = rank * JL + jl;
    const int bglob = gid * BG + b;

    // ---- mbarriers: count=1 (the arm is the arrival); arm phase 0 ----------
    if (tid == 0) {
        mbar_init(mb0, 1);
        mbar_init(mb1, 1);
        asm volatile("fence.mbarrier_init.release.cluster;" ::: "memory");
        mbar_arrive_tx(mb0, TXB);
        mbar_arrive_tx(mb1, TXB);
    }

    // ---- preload weight slices (j-slice = rank*16..rank*16+15) -------------
    for (int e = tid; e < 128 * 16 * 4; e += NT) {
        int kp = e & 127, r = e >> 7;
        int wjl = r >> 2, gsel = r & 3;
        int row = (gsel * HID + rank * JL + wjl) * HID + 2 * kp;
        int slot = (kp * 16 + wjl) * 4 + gsel;
        w0u [slot] = pack2(Whh0[row], Whh0[row + 1]);
        wi1u[slot] = pack2(Wih1[row], Wih1[row + 1]);
        wh1u[slot] = pack2(Whh1[row], Whh1[row + 1]);
    }
    for (int e = tid; e < JL * IN0; e += NT) {
        int wjl = e / IN0, d = e % IN0;
        int jg = rank * JL + wjl;
        wi0[wjl * IN0 + d] = make_float4(
            Wih0[(0*HID + jg)*IN0 + d], Wih0[(1*HID + jg)*IN0 + d],
            Wih0[(2*HID + jg)*IN0 + d], Wih0[(3*HID + jg)*IN0 + d]);
    }

    // ---- initial h (full group slice, [kp][b][2] layout), x[0] -------------
    for (int q = tid; q < 2048; q += NT) {
        int kp = q >> 4, bb = (q >> 1) & 7, pr = q & 1;
        int k = kp*2 + pr;
        sh_h0f[q] = h0in[(gid*BG + bb)*HID + k];
        sh_h1f[q] = h0in[(BATCH + gid*BG + bb)*HID + k];
    }
    for (int e = tid; e < BG*IN0; e += NT)
        shx[e] = x[(size_t)gid*BG*IN0 + e];

    // ---- per-role state ----------------------------------------------------
    float bs0=0.f, bs1=0.f, bs2=0.f, bs3=0.f, cst=0.f;
    if (kq == 0) {
        bs0 = bih0[0*HID+jglob] + bhh0[0*HID+jglob];
        bs1 = bih0[1*HID+jglob] + bhh0[1*HID+jglob];
        bs2 = bih0[2*HID+jglob] + bhh0[2*HID+jglob];
        bs3 = bih0[3*HID+jglob] + bhh0[3*HID+jglob];
        cst = c0[bglob*HID + jglob];
    } else if (kq == 1) {
        bs0 = bih1[0*HID+jglob] + bhh1[0*HID+jglob];
        bs1 = bih1[1*HID+jglob] + bhh1[1*HID+jglob];
        bs2 = bih1[2*HID+jglob] + bhh1[2*HID+jglob];
        bs3 = bih1[3*HID+jglob] + bhh1[3*HID+jglob];
        cst = c0[(BATCH + bglob)*HID + jglob];
    }
    const float wfcA = Wfc[f], wfcB = Wfc[f+128], bfc0 = bfc[0];

    __syncthreads();
    CLUSTER_ARRIVE(); CLUSTER_WAIT();   // smem + armed mbarriers visible

    // ---- sender setup: tid<256 send; L=tid>>7 (0:h0,1:h1); fixed dest ------
    uint32_t s_dadr = 0, s_dmb = 0; const float4* s_src = 0;
    if (tid < 256) {
        int L = tid >> 7, r = tid & 127, dest = r >> 3;
        uint32_t lbase = sb + (uint32_t)(L ? SH_H1 : SH_H0) + (uint32_t)rank * 512u;
        s_dadr = mapa_(lbase, (uint32_t)dest);
        s_dmb  = mapa_(L ? mb1 : mb0, (uint32_t)dest);
        s_src  = (const float4*)(L ? stg1 : stg0);
    }
    const int stgIdx = ((jl >> 1)*16) + b*2 + (jl & 1);   // float idx in 512B slice

    for (int t = 0; t <= S_LEN; ++t) {
        // ---- acquire h0[t-1] (completion t-1); arm phase t -----------------
        if (t >= 1) {
            mbar_wait_parity(mb0, (uint32_t)((t-1) & 1));
            if (tid == 0 && t < S_LEN) mbar_arrive_tx(mb0, TXB);
        }

        // ---- layer0 k-quarter (all roles) ----------------------------------
        unsigned long long a0=0,a1=0,a2=0,a3=0;
        if (t < S_LEN)
            gemmN<32>(sh_h0u + kq*32*8 + b, w0u + kq*32*64 + jl*4, a0,a1,a2,a3);
        float l0x=sum2(a0), l0y=sum2(a1), l0z=sum2(a2), l0w=sum2(a3);

        if (kq == 3) {
            if (t < S_LEN) {
                const float*  xr = shx + (t & 1)*(BG*IN0) + b*IN0;
                const float4* wi = wi0 + jl*IN0;
                #pragma unroll
                for (int d = 0; d < IN0; ++d) {
                    float xv = xr[d]; float4 w = wi[d];
                    l0x = fmaf(xv, w.x, l0x); l0y = fmaf(xv, w.y, l0y);
                    l0z = fmaf(xv, w.z, l0z); l0w = fmaf(xv, w.w, l0w);
                }
            }
            if (t + 1 < S_LEN && f < BG*IN0)
                shx[((t+1)&1)*(BG*IN0) + f] =
                    x[((size_t)(t+1)*BATCH + gid*BG)*IN0 + f];
        }
        if (kq != 0) pl0[(kq-1)*128 + f] = make_float4(l0x, l0y, l0z, l0w);

        // ---- layer1 half-GEMMs + FC ----------------------------------------
        unsigned long long e0=0,e1=0,e2=0,e3=0;
        if (kq == 0) {
            if (t >= 1) gemmN<64>(sh_h0u + b, wi1u + jl*4, e0,e1,e2,e3);
            pl1[f] = make_float4(sum2(e0), sum2(e1), sum2(e2), sum2(e3));
        } else if (kq == 1) {
            if (t >= 1) gemmN<64>(sh_h0u + 64*8 + b, wi1u + 64*64 + jl*4, e0,e1,e2,e3);
            if (t >= 2) {
                mbar_wait_parity(mb1, (uint32_t)((t-2) & 1));   // h1[t-2] here
                if (tid == 128) mbar_arrive_tx(mb1, TXB);       // arm next
                if (rank < BG) {          // FC for out[t-2], batch gid*8+rank
                    int j1 = f, j2 = f + 128;
                    float vA = sh_h1f[(j1>>1)*16 + rank*2 + (j1&1)];
                    float vB = sh_h1f[(j2>>1)*16 + rank*2 + (j2&1)];
                    float p = fmaxf(vA, 0.f)*wfcA + fmaxf(vB, 0.f)*wfcB;
                    p = warp_reduce(p);
                    if ((f & 31) == 0) red4[f >> 5] = p;
                    asm volatile("bar.sync 2, 128;" ::: "memory");
                    if (f == 0)
                        out[(size_t)(t-2)*BATCH + gid*BG + rank] =
                            red4[0]+red4[1]+red4[2]+red4[3] + bfc0;
                }
            }
        } else {
            if (t >= 2) mbar_wait_parity(mb1, (uint32_t)((t-2) & 1));
            if (t >= 1) gemmN<64>(sh_h1u + (kq-2)*64*8 + b,
                                  wh1u + (kq-2)*64*64 + jl*4, e0,e1,e2,e3);
            pl1[(kq-1)*128 + f] = make_float4(sum2(e0), sum2(e1), sum2(e2), sum2(e3));
        }

        __syncthreads();                 // combine; all local h reads done

        if (kq == 0) {
            if (t < S_LEN) {             // finalize layer0 -> stg0
                float4 p1 = pl0[f], p2 = pl0[128+f], p3 = pl0[256+f];
                float gi = l0x + p1.x + p2.x + p3.x + bs0;
                float gf = l0y + p1.y + p2.y + p3.y + bs1;
                float gg = l0z + p1.z + p2.z + p3.z + bs2;
                float go = l0w + p1.w + p2.w + p3.w + bs3;
                gi = sigmoidf_(gi); gf = sigmoidf_(gf);
                gg = tanh_acc(gg);  go = sigmoidf_(go);
                cst = gf*cst + gi*gg;
                stg0[stgIdx] = go * tanh_acc(cst);
            }
        } else if (kq == 1) {
            if (t >= 1) {                // finalize layer1 -> stg1
                float4 p1 = pl1[f], p2 = pl1[128+f], p3 = pl1[256+f];
                float gi = sum2(e0) + p1.x + p2.x + p3.x + bs0;
                float gf = sum2(e1) + p1.y + p2.y + p3.y + bs1;
                float gg = sum2(e2) + p1.z + p2.z + p3.z + bs2;
                float go = sum2(e3) + p1.w + p2.w + p3.w + bs3;
                gi = sigmoidf_(gi); gf = sigmoidf_(gf);
                gg = tanh_acc(gg);  go = sigmoidf_(go);
                cst = gf*cst + gi*gg;
                stg1[stgIdx] = go * tanh_acc(cst);
            }
        }

        // ---- cluster barrier: every peer finished reading h buffers,
        //      every peer armed its next phases -> safe to send --------------
        CLUSTER_ARRIVE(); CLUSTER_WAIT();

        // ---- broadcast this CTA's slices: 8 threads/dest x 4 chunks --------
        if (tid < 256 && ((tid < 128) ? (t < S_LEN) : (t >= 1))) {
            int r = tid & 7;
            #pragma unroll
            for (int q4 = 0; q4 < 4; ++q4) {
                int c = r + q4*8;
                st_async16(s_dadr + (uint32_t)c*16u, s_src[c], s_dmb);
            }
        }
    }

    // ---- final FC: out[S_LEN-1] from h1[S_LEN-1] (completion S_LEN-1) ------
    mbar_wait_parity(mb1, (uint32_t)((S_LEN-1) & 1));
    if (kq == 1 && rank < BG) {
        int j1 = f, j2 = f + 128;
        float vA = sh_h1f[(j1>>1)*16 + rank*2 + (j1&1)];
        float vB = sh_h1f[(j2>>1)*16 + rank*2 + (j2&1)];
        float p = fmaxf(vA, 0.f)*wfcA + fmaxf(vB, 0.f)*wfcB;
        p = warp_reduce(p);
        if ((f & 31) == 0) red4[f >> 5] = p;
        asm volatile("bar.sync 2, 128;" ::: "memory");
        if (f == 0)
            out[(size_t)(S_LEN-1)*BATCH + gid*BG + rank] =
                red4[0]+red4[1]+red4[2]+red4[3] + bfc0;
    }
    CLUSTER_ARRIVE(); CLUSTER_WAIT();    // keep smem alive until all landed
}

// ---------------------------------------------------------------------------
extern "C" void kernel_launch(void* const* d_in, const int* in_sizes, int n_in,
                              void* d_out, int out_size)
{
    const float* x    = (const float*)d_in[0];
    const float* h0   = (const float*)d_in[1];
    const float* c0   = (const float*)d_in[2];
    const float* Wih0 = (const float*)d_in[3];
    const float* Whh0 = (const float*)d_in[4];
    const float* bih0 = (const float*)d_in[5];
    const float* bhh0 = (const float*)d_in[6];
    const float* Wih1 = (const float*)d_in[7];
    const float* Whh1 = (const float*)d_in[8];
    const float* bih1 = (const float*)d_in[9];
    const float* bhh1 = (const float*)d_in[10];
    const float* Wfc  = (const float*)d_in[11];
    const float* bfc  = (const float*)d_in[12];
    float* out = (float*)d_out;

    cudaFuncSetAttribute(lstm_cluster,
                         cudaFuncAttributeMaxDynamicSharedMemorySize, SMEM_TOTAL);
    cudaFuncSetAttribute(lstm_cluster,
                         cudaFuncAttributeNonPortableClusterSizeAllowed, 1);

    cudaLaunchConfig_t cfg = {};
    cfg.gridDim  = dim3(NB, 1, 1);
    cfg.blockDim = dim3(NT, 1, 1);
    cfg.dynamicSmemBytes = SMEM_TOTAL;
    cfg.stream = 0;
    cudaLaunchAttribute attrs[1];
    attrs[0].id = cudaLaunchAttributeClusterDimension;
    attrs[0].val.clusterDim.x = GCTAS;
    attrs[0].val.clusterDim.y = 1;
    attrs[0].val.clusterDim.z = 1;
    cfg.attrs = attrs;
    cfg.numAttrs = 1;

    cudaLaunchKernelEx(&cfg, lstm_cluster,
                       x, h0, c0, Wih0, Whh0, bih0, bhh0,
                       Wih1, Whh1, bih1, bhh1, Wfc, bfc, out);
}

// round 17
// speedup vs baseline: 1.9278x; 1.9278x over previous
#include <cuda_runtime.h>
#include <cstdint>

// ---------------------------------------------------------------------------
// Fused 2-layer LSTM, S=4096, B=64, I=14, H=256, O=1 (gate order i,f,g,o)
// 8 groups x 16 CTAs. Two decoupled engines per CTA:
//   lo (tid<256):  layer0 recurrence. hi (tid>=256): layer1 + FC, lagging
//   1..3 steps behind via 4-slot global rings + monotone flags.
// Per-thread: pair p=(jl,b) of this CTA's 16 j x 8 b; kh splits k in half.
// ---------------------------------------------------------------------------

#define S_LEN 4096
#define BATCH 64
#define IN0   14
#define HID   256
#define NB    128
#define NT    512
#define GCTAS 16
#define BG    8

__device__ float    g_h0r[8][4][2048];   // ring, [kp][b][2] layout per slot
__device__ float    g_h1r[8][4][2048];
__device__ unsigned g_f0[8*32], g_f1[8*32];

static __device__ __forceinline__ unsigned long long pack2(float x, float y) {
    unsigned long long r; asm("mov.b64 %0, {%1,%2};" : "=l"(r) : "f"(x), "f"(y)); return r;
}
static __device__ __forceinline__ void unpack2(unsigned long long v, float& x, float& y) {
    asm("mov.b64 {%0,%1}, %2;" : "=f"(x), "=f"(y) : "l"(v));
}
static __device__ __forceinline__ unsigned long long ffma2(unsigned long long a,
        unsigned long long b, unsigned long long c) {
    unsigned long long d;
    asm("fma.rn.f32x2 %0, %1, %2, %3;" : "=l"(d) : "l"(a), "l"(b), "l"(c));
    return d;
}
static __device__ __forceinline__ float sum2(unsigned long long v) {
    float lo, hi; unpack2(v, lo, hi); return lo + hi;
}
static __device__ __forceinline__ float sigmoidf_(float v) {
    return 1.0f / (1.0f + __expf(-v));
}
static __device__ __forceinline__ float tanh_acc(float v) {
    float a = fabsf(v), e = __expf(-2.0f * a);
    float r = __fdividef(1.0f - e, 1.0f + e);
    return v < 0.0f ? -r : r;
}
static __device__ __forceinline__ float warp_reduce(float p) {
    #pragma unroll
    for (int o = 16; o > 0; o >>= 1) p += __shfl_xor_sync(0xffffffffu, p, o);
    return p;
}
static __device__ __forceinline__ void red_rel_add(unsigned* p) {
    asm volatile("red.release.gpu.global.add.u32 [%0], %1;" :: "l"(p), "r"(1u) : "memory");
}
static __device__ __forceinline__ unsigned ld_acq(const unsigned* p) {
    unsigned v;
    asm volatile("ld.acquire.gpu.global.u32 %0, [%1];" : "=r"(v) : "l"(p) : "memory");
    return v;
}
static __device__ __forceinline__ void cp16(uint32_t dst, const void* src) {
    asm volatile("cp.async.cg.shared.global [%0], [%1], 16;" :: "r"(dst), "l"(src));
}
static __device__ __forceinline__ void mbar_init(uint32_t a, uint32_t cnt) {
    asm volatile("mbarrier.init.shared.b64 [%0], %1;" :: "r"(a), "r"(cnt) : "memory");
}
static __device__ __forceinline__ void cp_arrive_noinc(uint32_t a) {
    asm volatile("cp.async.mbarrier.arrive.noinc.shared.b64 [%0];" :: "r"(a) : "memory");
}
static __device__ __forceinline__ void mbar_wait_parity(uint32_t addr, uint32_t parity) {
    asm volatile(
        "{\n\t.reg .pred P;\nMW_%=:\n\t"
        "mbarrier.try_wait.parity.shared::cta.b64 P, [%0], %1;\n\t"
        "@!P bra MW_%=;\n\t}" :: "r"(addr), "r"(parity) : "memory");
}
#define BARL() asm volatile("bar.sync 1, 256;" ::: "memory")
#define BARH() asm volatile("bar.sync 2, 256;" ::: "memory")

template<int N>
static __device__ __forceinline__ void gemmN(const unsigned long long* hp,
        const unsigned long long* wq,
        unsigned long long& a0, unsigned long long& a1,
        unsigned long long& a2, unsigned long long& a3) {
    #pragma unroll 8
    for (int kp = 0; kp < N; ++kp) {
        unsigned long long hv = hp[kp*8];
        const unsigned long long* w = wq + kp*64;
        ulonglong2 wA = *(const ulonglong2*)(w);
        ulonglong2 wB = *(const ulonglong2*)(w + 2);
        a0 = ffma2(hv, wA.x, a0); a1 = ffma2(hv, wA.y, a1);
        a2 = ffma2(hv, wB.x, a2); a3 = ffma2(hv, wB.y, a3);
    }
}

// smem layout (bytes)
#define SH_W0    0          // 65536  Whh0  ull slot (kp*16+jl)*4+gate
#define SH_WI1   65536      // 65536
#define SH_WH1   131072     // 65536
#define SH_WI0   196608     // 3584   float4[16][14]
#define SH_H0A   200192     // 8192   layer0's h0 view
#define SH_H0B   208384     // 8192   layer1's h0 view
#define SH_H1    216576     // 8192   layer1's h1 view
#define SH_PL0   224768     // 2048   float4[128]
#define SH_PL1   226816     // 2048
#define SH_X     228864     // 896    float[2][112]
#define SH_RED   229760     // 32
#define SH_MBAR  229792     // 24     m0a, m0b, m1
#define SMEM_TOTAL 229816

extern "C" __global__ void __launch_bounds__(NT, 1)
lstm_df(const float* __restrict__ x,    const float* __restrict__ c0,
        const float* __restrict__ Wih0, const float* __restrict__ Whh0,
        const float* __restrict__ bih0, const float* __restrict__ bhh0,
        const float* __restrict__ Wih1, const float* __restrict__ Whh1,
        const float* __restrict__ bih1, const float* __restrict__ bhh1,
        const float* __restrict__ Wfc,  const float* __restrict__ bfc,
        float* __restrict__ out)
{
    extern __shared__ char smem[];
    unsigned long long* w0u  = (unsigned long long*)(smem + SH_W0);
    unsigned long long* wi1u = (unsigned long long*)(smem + SH_WI1);
    unsigned long long* wh1u = (unsigned long long*)(smem + SH_WH1);
    float4*  wi0   = (float4*)(smem + SH_WI0);
    unsigned long long* h0au = (unsigned long long*)(smem + SH_H0A);
    unsigned long long* h0bu = (unsigned long long*)(smem + SH_H0B);
    unsigned long long* h1u  = (unsigned long long*)(smem + SH_H1);
    float*   h1f   = (float*)(smem + SH_H1);
    float4*  pl0   = (float4*)(smem + SH_PL0);
    float4*  pl1   = (float4*)(smem + SH_PL1);
    float*   shx   = (float*)(smem + SH_X);
    float*   red8  = (float*)(smem + SH_RED);

    const uint32_t sb  = (uint32_t)__cvta_generic_to_shared(smem);
    const uint32_t m0a = sb + SH_MBAR, m0b = m0a + 8, m1 = m0a + 16;

    const int tid = threadIdx.x;
    const int gid = blockIdx.x >> 4;
    const int ci  = blockIdx.x & 15;

    if (tid == 0) { mbar_init(m0a, 256); mbar_init(m0b, 256); mbar_init(m1, 256); }

    // weight preload (all threads)
    for (int e = tid; e < 128*16*4; e += NT) {
        int kp = e & 127, r = e >> 7, wjl = r >> 2, gs = r & 3;
        int row = (gs*HID + ci*16 + wjl)*HID + 2*kp;
        int slot = (kp*16 + wjl)*4 + gs;
        w0u [slot] = pack2(Whh0[row], Whh0[row+1]);
        wi1u[slot] = pack2(Wih1[row], Wih1[row+1]);
        wh1u[slot] = pack2(Whh1[row], Whh1[row+1]);
    }
    for (int e = tid; e < 16*IN0; e += NT) {
        int wjl = e / IN0, d = e % IN0, jg = ci*16 + wjl;
        wi0[wjl*IN0 + d] = make_float4(
            Wih0[(0*HID+jg)*IN0+d], Wih0[(1*HID+jg)*IN0+d],
            Wih0[(2*HID+jg)*IN0+d], Wih0[(3*HID+jg)*IN0+d]);
    }
    if (tid < 112) shx[tid] = x[(size_t)(gid*BG)*IN0 + tid];   // x[0]
    __syncthreads();

    unsigned* f0 = &g_f0[gid*32];
    unsigned* f1 = &g_f1[gid*32];

    if (tid < 256) {
        // ================= layer0 engine ================================
        const int p = tid & 127, kh = tid >> 7, jl = p >> 3, b = p & 7;
        const int jg = ci*16 + jl;
        float bs0=0,bs1=0,bs2=0,bs3=0,cst=0;
        if (kh == 0) {
            bs0 = bih0[0*HID+jg] + bhh0[0*HID+jg];
            bs1 = bih0[1*HID+jg] + bhh0[1*HID+jg];
            bs2 = bih0[2*HID+jg] + bhh0[2*HID+jg];
            bs3 = bih0[3*HID+jg] + bhh0[3*HID+jg];
            cst = c0[(gid*BG + b)*HID + jg];
        }
        const int stIdx = (jg >> 1)*16 + b*2 + (jg & 1);
        for (int t = 0; t < S_LEN; ++t) {
            const uint32_t par = (uint32_t)(t & 1);
            if (tid == 0) {
                if (t >= 1) { unsigned tgt = 16u*(unsigned)t;
                    while (ld_acq(f0) < tgt) { } }
                if (t >= 4) { unsigned tgt = 16u*(unsigned)(t-3);
                    while (ld_acq(f1) < tgt) { } }
            }
            BARL();
            { const float4* s0 = (const float4*)g_h0r[gid][(t+3)&3];
              cp16(sb + SH_H0A + tid*32,      s0 + tid*2);
              cp16(sb + SH_H0A + tid*32 + 16, s0 + tid*2 + 1);
              cp_arrive_noinc(m0a); }
            mbar_wait_parity(m0a, par);
            unsigned long long a0=0,a1=0,a2=0,a3=0;
            gemmN<64>(h0au + kh*64*8 + b, w0u + kh*64*64 + jl*4, a0,a1,a2,a3);
            float lx=sum2(a0), ly=sum2(a1), lz=sum2(a2), lw=sum2(a3);
            if (kh == 1) {
                const float*  xr = shx + (t&1)*112 + b*IN0;
                const float4* wi = wi0 + jl*IN0;
                #pragma unroll
                for (int d = 0; d < IN0; ++d) {
                    float xv = xr[d]; float4 w = wi[d];
                    lx = fmaf(xv,w.x,lx); ly = fmaf(xv,w.y,ly);
                    lz = fmaf(xv,w.z,lz); lw = fmaf(xv,w.w,lw);
                }
                pl0[p] = make_float4(lx,ly,lz,lw);
                if (t+1 < S_LEN && p < 112)
                    shx[((t+1)&1)*112 + p] =
                        x[((size_t)(t+1)*BATCH + gid*BG)*IN0 + p];
            }
            BARL();
            if (kh == 0) {
                float4 q = pl0[p];
                float gi = sigmoidf_(lx + q.x + bs0);
                float gf = sigmoidf_(ly + q.y + bs1);
                float gg = tanh_acc (lz + q.z + bs2);
                float go = sigmoidf_(lw + q.w + bs3);
                cst = gf*cst + gi*gg;
                g_h0r[gid][t&3][stIdx] = go * tanh_acc(cst);
            }
            BARL();
            if (tid == 0) red_rel_add(f0);
        }
    } else {
        // ================= layer1 engine + FC ===========================
        const int f2 = tid - 256;
        const int p = f2 & 127, kh = f2 >> 7, jl = p >> 3, b = p & 7;
        const int jg = ci*16 + jl;
        float bs0=0,bs1=0,bs2=0,bs3=0,cst=0;
        if (kh == 0) {
            bs0 = bih1[0*HID+jg] + bhh1[0*HID+jg];
            bs1 = bih1[1*HID+jg] + bhh1[1*HID+jg];
            bs2 = bih1[2*HID+jg] + bhh1[2*HID+jg];
            bs3 = bih1[3*HID+jg] + bhh1[3*HID+jg];
            cst = c0[(BATCH + gid*BG + b)*HID + jg];
        }
        const float wfc = Wfc[f2], bfc0 = bfc[0];
        const int stIdx = (jg >> 1)*16 + b*2 + (jg & 1);
        for (int t1 = 1; t1 <= S_LEN + 1; ++t1) {
            const uint32_t par = (uint32_t)((t1-1) & 1);
            const bool last = (t1 == S_LEN + 1);
            if (tid == 256) {
                if (!last) { unsigned tgt = 16u*(unsigned)t1;
                    while (ld_acq(f0) < tgt) { } }
                { unsigned tgt = 16u*(unsigned)(t1-1);
                  while (ld_acq(f1) < tgt) { } }
            }
            BARH();
            if (!last) {
                const float4* s0 = (const float4*)g_h0r[gid][(t1+3)&3];
                cp16(sb + SH_H0B + f2*32,      s0 + f2*2);
                cp16(sb + SH_H0B + f2*32 + 16, s0 + f2*2 + 1);
                cp_arrive_noinc(m0b);
            }
            { const float4* s1 = (const float4*)g_h1r[gid][(t1+2)&3];
              cp16(sb + SH_H1 + f2*32,      s1 + f2*2);
              cp16(sb + SH_H1 + f2*32 + 16, s1 + f2*2 + 1);
              cp_arrive_noinc(m1); }
            unsigned long long e0=0,e1=0,e2=0,e3=0;
            if (!last) {
                mbar_wait_parity(m0b, par);
                gemmN<64>(h0bu + kh*64*8 + b, wi1u + kh*64*64 + jl*4, e0,e1,e2,e3);
            }
            mbar_wait_parity(m1, par);
            if (!last) {
                gemmN<64>(h1u + kh*64*8 + b, wh1u + kh*64*64 + jl*4, e0,e1,e2,e3);
                if (kh == 1)
                    pl1[p] = make_float4(sum2(e0),sum2(e1),sum2(e2),sum2(e3));
            }
            BARH();
            if (!last && kh == 0) {
                float4 q = pl1[p];
                float gi = sigmoidf_(sum2(e0) + q.x + bs0);
                float gf = sigmoidf_(sum2(e1) + q.y + bs1);
                float gg = tanh_acc (sum2(e2) + q.z + bs2);
                float go = sigmoidf_(sum2(e3) + q.w + bs3);
                cst = gf*cst + gi*gg;
                g_h1r[gid][(t1-1)&3][stIdx] = go * tanh_acc(cst);
            }
            BARH();
            if (!last && tid == 256) red_rel_add(f1);
            if (t1 >= 2) {            // FC: out[t1-2] from SH_H1 = h1[t1-2]
                float v = h1f[(f2>>1)*16 + ci*2 + (f2&1)];
                float pr = fmaxf(v, 0.f) * wfc;
                pr = warp_reduce(pr);
                if ((f2 & 31) == 0) red8[f2 >> 5] = pr;
                BARH();
                if (tid == 256 && ci < BG) {
                    float s = red8[0]+red8[1]+red8[2]+red8[3]
                            + red8[4]+red8[5]+red8[6]+red8[7] + bfc0;
                    out[(size_t)(t1-2)*BATCH + gid*BG + ci] = s;
                }
            }
        }
    }
}

// init: rings slot 3 = initial h, flags = 0
extern "C" __global__ void lstm_init(const float* __restrict__ h0)
{
    int i = blockIdx.x * blockDim.x + threadIdx.x;
    if (i < 8*32) { g_f0[i] = 0u; g_f1[i] = 0u; }
    for (int idx = i; idx < 2*8*2048; idx += gridDim.x * blockDim.x) {
        int l = idx >> 14, r = idx & 16383, g = r >> 11, q = r & 2047;
        int kp = q >> 4, b = (q >> 1) & 7, pj = q & 1;
        int k = kp*2 + pj;
        float v = h0[(l*BATCH + g*BG + b)*HID + k];
        if (l == 0) g_h0r[g][3][q] = v; else g_h1r[g][3][q] = v;
    }
}

extern "C" void kernel_launch(void* const* d_in, const int* in_sizes, int n_in,
                              void* d_out, int out_size)
{
    const float* x    = (const float*)d_in[0];
    const float* h0   = (const float*)d_in[1];
    const float* c0   = (const float*)d_in[2];
    const float* Wih0 = (const float*)d_in[3];
    const float* Whh0 = (const float*)d_in[4];
    const float* bih0 = (const float*)d_in[5];
    const float* bhh0 = (const float*)d_in[6];
    const float* Wih1 = (const float*)d_in[7];
    const float* Whh1 = (const float*)d_in[8];
    const float* bih1 = (const float*)d_in[9];
    const float* bhh1 = (const float*)d_in[10];
    const float* Wfc  = (const float*)d_in[11];
    const float* bfc  = (const float*)d_in[12];
    float* out = (float*)d_out;

    cudaFuncSetAttribute(lstm_df, cudaFuncAttributeMaxDynamicSharedMemorySize,
                         SMEM_TOTAL);
    lstm_init<<<64, 256>>>(h0);
    lstm_df<<<NB, NT, SMEM_TOTAL>>>(x, c0, Wih0, Whh0, bih0, bhh0,
                                    Wih1, Whh1, bih1, bhh1, Wfc, bfc, out);
}